// round 10
// baseline (speedup 1.0000x reference)
#include <cuda_runtime.h>

#define EPS      1e-4f
#define FRAMES   4000
#define THREADS  256
#define TILE     (THREADS * 4)        // 1024 elements per tile
#define NTILES   4                    // 4 * 1024 = 4096 >= 4000
#define NWARPS   (THREADS / 32)       // 8

__global__ __launch_bounds__(THREADS)
void cumnorm_kernel(const float* __restrict__ x, float* __restrict__ out)
{
    __shared__ float2 wsum[NTILES * NWARPS];   // [tile][warp] inclusive (sum, sumsq)

    const int tid  = threadIdx.x;
    const int lane = tid & 31;
    const int warp = tid >> 5;

    const size_t rowoff = (size_t)blockIdx.x * FRAMES;
    const float* __restrict__ xin  = x   + rowoff;
    float*       __restrict__ xout = out + rowoff;

    // ---- issue ALL loads up front (coalesced float4, MLP=4 per thread) ----
    // tiles 0..2 fully in range; only tile 3 needs the guard
    float4 v[NTILES];
    #pragma unroll
    for (int k = 0; k < NTILES; ++k) {
        const int e = k * TILE + 4 * tid;
        if (k < NTILES - 1 || e < FRAMES)
            v[k] = *reinterpret_cast<const float4*>(xin + e);
        else
            v[k] = make_float4(0.f, 0.f, 0.f, 0.f);
    }

    // ---- per-tile thread totals straight into scan registers ----
    float is[NTILES], iq[NTILES];
    #pragma unroll
    for (int k = 0; k < NTILES; ++k) {
        const float4 vk = v[k];
        is[k] = (vk.x + vk.y) + (vk.z + vk.w);
        float q = vk.x * vk.x;
        q = fmaf(vk.y, vk.y, q);
        q = fmaf(vk.z, vk.z, q);
        iq[k] = fmaf(vk.w, vk.w, q);
    }

    // ---- 4 warp scans interleaved (8 independent shuffle chains) ----
    #pragma unroll
    for (int d = 1; d < 32; d <<= 1) {
        #pragma unroll
        for (int k = 0; k < NTILES; ++k) {
            float as = __shfl_up_sync(0xffffffffu, is[k], d);
            float aq = __shfl_up_sync(0xffffffffu, iq[k], d);
            if (lane >= d) { is[k] += as; iq[k] += aq; }
        }
    }

    if (lane == 31) {
        #pragma unroll
        for (int k = 0; k < NTILES; ++k)
            wsum[k * NWARPS + warp] = make_float2(is[k], iq[k]);
    }

    // ---- per-thread EXCLUSIVE prefix via one more shfl (lets is/iq die) ----
    float es[NTILES], eq[NTILES];
    #pragma unroll
    for (int k = 0; k < NTILES; ++k) {
        float as = __shfl_up_sync(0xffffffffu, is[k], 1);
        float aq = __shfl_up_sync(0xffffffffu, iq[k], 1);
        es[k] = (lane > 0) ? as : 0.f;
        eq[k] = (lane > 0) ? aq : 0.f;
    }
    __syncthreads();

    // ---- single segmented cross-warp scan: 32 entries = 4 segments of 8 ----
    if (warp == 0) {
        float2 w = wsum[lane];
        float ws = w.x, wq = w.y;
        #pragma unroll
        for (int d = 1; d < NWARPS; d <<= 1) {
            float as = __shfl_up_sync(0xffffffffu, ws, d);
            float aq = __shfl_up_sync(0xffffffffu, wq, d);
            if ((lane & (NWARPS - 1)) >= d) { ws += as; wq += aq; }
        }
        wsum[lane] = make_float2(ws, wq);
    }
    __syncthreads();

    // ---- tail: carry accumulated incrementally from smem (broadcast reads) ----
    float cs = 0.f, cq = 0.f;
    #pragma unroll
    for (int k = 0; k < NTILES; ++k) {
        const float2 wp = (warp > 0) ? wsum[k * NWARPS + warp - 1]
                                     : make_float2(0.f, 0.f);
        float ps = cs + wp.x + es[k];
        float pq = cq + wp.y + eq[k];

        const float2 tot = wsum[k * NWARPS + (NWARPS - 1)];
        cs += tot.x;
        cq += tot.y;

        const int e = k * TILE + 4 * tid;
        if (k < NTILES - 1 || e < FRAMES) {
            float r[4] = {v[k].x, v[k].y, v[k].z, v[k].w};
            float c = (float)e;
            #pragma unroll
            for (int j = 0; j < 4; ++j) {
                const float xv = r[j];
                ps += xv;
                pq  = fmaf(xv, xv, pq);
                c  += 1.f;
                const float ecc = (EPS * c) * c;
                const float den = fmaf(c, pq, fmaf(-ps, ps, ecc)); // c*q - s^2 + eps*c^2
                const float num = fmaf(c, xv, -ps);                // c*x - s
                r[j] = num * rsqrtf(den);
            }
            *reinterpret_cast<float4*>(xout + e) =
                make_float4(r[0], r[1], r[2], r[3]);
        }
    }
}

extern "C" void kernel_launch(void* const* d_in, const int* in_sizes, int n_in,
                              void* d_out, int out_size)
{
    const float* x = (const float*)d_in[0];
    float* outp    = (float*)d_out;
    const int rows = in_sizes[0] / FRAMES;   // 32 * 512 = 16384
    cumnorm_kernel<<<rows, THREADS>>>(x, outp);
}